// round 14
// baseline (speedup 1.0000x reference)
#include <cuda_runtime.h>
#include <cstdint>

// Householder reflection per row, B=8192, L=4096, fp32.
//   out[b,:] = z[b,:] - 2 * v[b,:] * (v.z)/(v.v)
//
// R13: persistent CTAs (456 = 152 SMs x 3) with double-buffered TMA stages.
// Each CTA owns 2 x 32KB stages; the refill TMA for row i+2 is issued at the
// reduction barrier of row i (the earliest point all threads have consumed
// the stage), so every CTA keeps a bulk-load stream alive continuously —
// unlike the fire-once kernels whose streams die at the mbarrier wait.
// Payload lives in smem + registers-per-row only (no R2 spill); 3 independent
// CTAs/SM avoid R4's whole-SM barrier coupling.

constexpr int THREADS  = 256;
constexpr int L        = 4096;
constexpr int L4       = L / 4;            // 1024 float4 per row
constexpr int PER      = L4 / THREADS;     // 4 float4 per thread per tensor
constexpr int STAGES   = 2;
constexpr int ROW_BYTES = L * 4;           // 16384
constexpr int STAGE_F4  = 2 * L4;          // v + z = 2048 float4 = 32KB
constexpr size_t SMEM_BYTES = (size_t)STAGES * STAGE_F4 * sizeof(float4); // 64KB
constexpr int GRID_MAX  = 152 * 3;         // 3 CTAs per SM (smem-limited)

__device__ __forceinline__ uint32_t smem_u32(const void* p) {
    return (uint32_t)__cvta_generic_to_shared(p);
}

__device__ __forceinline__ void mbar_wait(uint32_t mb, uint32_t ph) {
    uint32_t done;
    asm volatile(
        "{\n\t.reg .pred p;\n\t"
        "mbarrier.try_wait.parity.acquire.cta.shared::cta.b64 p, [%1], %2;\n\t"
        "selp.b32 %0, 1, 0, p;\n\t}"
        : "=r"(done) : "r"(mb), "r"(ph) : "memory");
    while (!done) {
        asm volatile(
            "{\n\t.reg .pred p;\n\t"
            "mbarrier.try_wait.parity.acquire.cta.shared::cta.b64 p, [%1], %2, 0x989680;\n\t"
            "selp.b32 %0, 1, 0, p;\n\t}"
            : "=r"(done) : "r"(mb), "r"(ph) : "memory");
    }
}

__global__ __launch_bounds__(THREADS)
void hh_tma_r13_kernel(const float4* __restrict__ v,
                       const float4* __restrict__ z,
                       float4* __restrict__ out,
                       int B)
{
    extern __shared__ float4 sm[];   // stage s: v [s*2048, +1024), z [+1024, +2048)
    __shared__ __align__(8) unsigned long long mbar[STAGES];
    __shared__ float s_part[16];     // 8 warps x {vz, vv}
    __shared__ float s_scale;

    const int t    = threadIdx.x;
    const int lane = t & 31;
    const int wid  = t >> 5;
    const int bid  = blockIdx.x;
    const int grid = gridDim.x;

    if (t == 0) {
        asm volatile("mbarrier.init.shared::cta.b64 [%0], %1;"
                     :: "r"(smem_u32(&mbar[0])), "r"(1));
        asm volatile("mbarrier.init.shared::cta.b64 [%0], %1;"
                     :: "r"(smem_u32(&mbar[1])), "r"(1));
        asm volatile("fence.proxy.async.shared::cta;" ::: "memory");
    }
    __syncthreads();

    auto issue = [&](int iter) {
        const int row = bid + iter * grid;
        if (row < B) {
            const int s = iter & 1;
            const uint32_t mb = smem_u32(&mbar[s]);
            float4* vs = sm + (size_t)s * STAGE_F4;
            const size_t base = (size_t)row * L4;
            asm volatile("mbarrier.arrive.expect_tx.shared::cta.b64 _, [%0], %1;"
                         :: "r"(mb), "r"(2 * ROW_BYTES) : "memory");
            asm volatile("cp.async.bulk.shared::cta.global.mbarrier::complete_tx::bytes"
                         " [%0], [%1], %2, [%3];"
                         :: "r"(smem_u32(vs)), "l"(v + base),
                            "r"(ROW_BYTES), "r"(mb) : "memory");
            asm volatile("cp.async.bulk.shared::cta.global.mbarrier::complete_tx::bytes"
                         " [%0], [%1], %2, [%3];"
                         :: "r"(smem_u32(vs + L4)), "l"(z + base),
                            "r"(ROW_BYTES), "r"(mb) : "memory");
        }
    };

    // Prologue: fill both stages
    if (t == 0) { issue(0); issue(1); }

    const int niter = (B - bid + grid - 1) / grid;

    for (int i = 0; i < niter; i++) {
        const int s  = i & 1;
        const uint32_t ph = (i >> 1) & 1;
        mbar_wait(smem_u32(&mbar[s]), ph);

        const float4* vs = sm + (size_t)s * STAGE_F4;
        const float4* zs = vs + L4;

        // Single smem pass: payload into registers, both dots
        float4 rv[PER], rz[PER];
        float dvz = 0.0f, dvv = 0.0f;
        #pragma unroll
        for (int k = 0; k < PER; k++) {
            rv[k] = vs[t + k * THREADS];
            rz[k] = zs[t + k * THREADS];
            dvz += rv[k].x * rz[k].x + rv[k].y * rz[k].y
                 + rv[k].z * rz[k].z + rv[k].w * rz[k].w;
            dvv += rv[k].x * rv[k].x + rv[k].y * rv[k].y
                 + rv[k].z * rv[k].z + rv[k].w * rv[k].w;
        }

        #pragma unroll
        for (int off = 16; off > 0; off >>= 1) {
            dvz += __shfl_xor_sync(0xFFFFFFFFu, dvz, off);
            dvv += __shfl_xor_sync(0xFFFFFFFFu, dvv, off);
        }
        if (lane == 0) { s_part[wid] = dvz; s_part[8 + wid] = dvv; }
        __syncthreads();   // all threads done reading stage s

        // Re-arm stage s for row i+2 immediately — stream stays alive
        if (t == 0) issue(i + 2);

        if (wid == 0) {
            float a = (lane < 8) ? s_part[lane] : 0.0f;
            float c = (lane < 8) ? s_part[8 + lane] : 0.0f;
            #pragma unroll
            for (int off = 4; off > 0; off >>= 1) {
                a += __shfl_xor_sync(0xFFFFFFFFu, a, off);
                c += __shfl_xor_sync(0xFFFFFFFFu, c, off);
            }
            if (lane == 0) s_scale = 2.0f * a / c;
        }
        __syncthreads();

        const float nscale = -s_scale;
        float4* og = out + (size_t)(bid + i * grid) * L4;

        #pragma unroll
        for (int k = 0; k < PER; k++) {
            float4 o;
            o.x = fmaf(nscale, rv[k].x, rz[k].x);
            o.y = fmaf(nscale, rv[k].y, rz[k].y);
            o.z = fmaf(nscale, rv[k].z, rz[k].z);
            o.w = fmaf(nscale, rv[k].w, rz[k].w);
            __stcs(og + t + k * THREADS, o);
        }
    }
}

extern "C" void kernel_launch(void* const* d_in, const int* in_sizes, int n_in,
                              void* d_out, int out_size)
{
    const float4* v = (const float4*)d_in[0];
    const float4* z = (const float4*)d_in[1];
    float4* out = (float4*)d_out;

    const int B = in_sizes[0] / L;    // 8192

    static bool attr_set = false;
    if (!attr_set) {
        cudaFuncSetAttribute(hh_tma_r13_kernel,
                             cudaFuncAttributeMaxDynamicSharedMemorySize,
                             (int)SMEM_BYTES);
        attr_set = true;
    }

    const int grid = (B < GRID_MAX) ? B : GRID_MAX;
    hh_tma_r13_kernel<<<grid, THREADS, SMEM_BYTES>>>(v, z, out, B);
}

// round 15
// speedup vs baseline: 1.1602x; 1.1602x over previous
#include <cuda_runtime.h>
#include <cstdint>

// Householder reflection per row, B=8192, L=4096, fp32.
//   out[b,:] = z[b,:] - 2 * v[b,:] * (v.z)/(v.v)
//
// R7 base (best wall 61.9us): one CTA per row, cp.async.bulk loads into smem
// (bypasses cross-CTA L1tex queue), register-resident payload, single smem
// pass. R15 change: stores are WRITE-THROUGH (__stwt). With __stcs the
// output accumulates as dirty L2 lines that drain AFTER kernel end — billed
// as the ~8us wall-vs-ncu gap on every graph replay. WT streams writes to
// DRAM during the kernel, shrinking the post-kernel drain tail.

constexpr int THREADS = 256;
constexpr int L       = 4096;
constexpr int L4      = L / 4;             // 1024 float4 per row
constexpr int PER     = L4 / THREADS;      // 4 float4 per thread per tensor
constexpr int ROW_BYTES   = L * 4;         // 16384
constexpr int STAGE_BYTES = 2 * ROW_BYTES; // 32768 (v + z)

__device__ __forceinline__ uint32_t smem_u32(const void* p) {
    return (uint32_t)__cvta_generic_to_shared(p);
}

__global__ __launch_bounds__(THREADS)
void hh_tma_r15_kernel(const float4* __restrict__ v,
                       const float4* __restrict__ z,
                       float4* __restrict__ out)
{
    extern __shared__ float4 sm[];            // v: [0,1024), z: [1024,2048)
    __shared__ __align__(8) unsigned long long mbar;
    __shared__ float s_part[16];              // 8 warps x {vz, vv}
    __shared__ float s_scale;

    const int t    = threadIdx.x;
    const int lane = t & 31;
    const int wid  = t >> 5;
    const size_t base = (size_t)blockIdx.x * L4;

    const uint32_t mb = smem_u32(&mbar);

    if (t == 0) {
        asm volatile("mbarrier.init.shared::cta.b64 [%0], %1;"
                     :: "r"(mb), "r"(1));
        asm volatile("fence.proxy.async.shared::cta;" ::: "memory");
    }
    __syncthreads();

    if (t == 0) {
        asm volatile("mbarrier.arrive.expect_tx.shared::cta.b64 _, [%0], %1;"
                     :: "r"(mb), "r"(STAGE_BYTES) : "memory");
        asm volatile("cp.async.bulk.shared::cta.global.mbarrier::complete_tx::bytes"
                     " [%0], [%1], %2, [%3];"
                     :: "r"(smem_u32(sm)), "l"(v + base), "r"(ROW_BYTES), "r"(mb)
                     : "memory");
        asm volatile("cp.async.bulk.shared::cta.global.mbarrier::complete_tx::bytes"
                     " [%0], [%1], %2, [%3];"
                     :: "r"(smem_u32(sm + L4)), "l"(z + base), "r"(ROW_BYTES), "r"(mb)
                     : "memory");
    }

    // Wait (parity 0, single-shot), acquire for generic smem reads
    {
        uint32_t done;
        asm volatile(
            "{\n\t.reg .pred p;\n\t"
            "mbarrier.try_wait.parity.acquire.cta.shared::cta.b64 p, [%1], %2;\n\t"
            "selp.b32 %0, 1, 0, p;\n\t}"
            : "=r"(done) : "r"(mb), "r"(0) : "memory");
        while (!done) {
            asm volatile(
                "{\n\t.reg .pred p;\n\t"
                "mbarrier.try_wait.parity.acquire.cta.shared::cta.b64 p, [%1], %2, 0x989680;\n\t"
                "selp.b32 %0, 1, 0, p;\n\t}"
                : "=r"(done) : "r"(mb), "r"(0) : "memory");
        }
    }

    // Single smem pass: payload into registers, both dots accumulated
    float4 rv[PER], rz[PER];
    float dvz = 0.0f, dvv = 0.0f;
    #pragma unroll
    for (int i = 0; i < PER; i++) {
        rv[i] = sm[t + i * THREADS];
        rz[i] = sm[L4 + t + i * THREADS];
        dvz += rv[i].x * rz[i].x + rv[i].y * rz[i].y
             + rv[i].z * rz[i].z + rv[i].w * rz[i].w;
        dvv += rv[i].x * rv[i].x + rv[i].y * rv[i].y
             + rv[i].z * rv[i].z + rv[i].w * rv[i].w;
    }

    #pragma unroll
    for (int off = 16; off > 0; off >>= 1) {
        dvz += __shfl_xor_sync(0xFFFFFFFFu, dvz, off);
        dvv += __shfl_xor_sync(0xFFFFFFFFu, dvv, off);
    }
    if (lane == 0) { s_part[wid] = dvz; s_part[8 + wid] = dvv; }
    __syncthreads();

    if (wid == 0) {
        float a = (lane < 8) ? s_part[lane] : 0.0f;
        float c = (lane < 8) ? s_part[8 + lane] : 0.0f;
        #pragma unroll
        for (int off = 4; off > 0; off >>= 1) {
            a += __shfl_xor_sync(0xFFFFFFFFu, a, off);
            c += __shfl_xor_sync(0xFFFFFFFFu, c, off);
        }
        if (lane == 0) s_scale = 2.0f * a / c;
    }
    __syncthreads();

    const float nscale = -s_scale;
    float4* og = out + base;

    // Output from registers; WRITE-THROUGH stores — drain during the kernel,
    // not as a post-kernel dirty-L2 tail billed to the next graph replay.
    #pragma unroll
    for (int i = 0; i < PER; i++) {
        float4 o;
        o.x = fmaf(nscale, rv[i].x, rz[i].x);
        o.y = fmaf(nscale, rv[i].y, rz[i].y);
        o.z = fmaf(nscale, rv[i].z, rz[i].z);
        o.w = fmaf(nscale, rv[i].w, rz[i].w);
        __stwt(og + t + i * THREADS, o);
    }
}

extern "C" void kernel_launch(void* const* d_in, const int* in_sizes, int n_in,
                              void* d_out, int out_size)
{
    const float4* v = (const float4*)d_in[0];
    const float4* z = (const float4*)d_in[1];
    float4* out = (float4*)d_out;

    const int B = in_sizes[0] / L;    // 8192

    static bool attr_set = false;
    if (!attr_set) {
        cudaFuncSetAttribute(hh_tma_r15_kernel,
                             cudaFuncAttributeMaxDynamicSharedMemorySize,
                             STAGE_BYTES);
        attr_set = true;
    }

    hh_tma_r15_kernel<<<B, THREADS, STAGE_BYTES>>>(v, z, out);
}